// round 16
// baseline (speedup 1.0000x reference)
#include <cuda_runtime.h>
#include <cuda_bf16.h>
#include <math.h>
#include <stdint.h>

// Gate_90426241450822: logits = x @ W ; y = softmax(logits) * top2_mask
// x: [M=16384, K=4096] fp32, W: [K=4096, E=64] fp32
// out: [y (M*64) | logits (M*64)] fp32
//
// R16 = R13 skeleton (best: 166us) with the A-path rebuilt:
//  - A: LDG.128 fp32 -> registers (1 tile ahead) -> split to bf16 hi/lo in
//    REGISTERS (off the MMA critical path, feeds tile t+1) -> STS into a
//    2-stage bf16 smem ring -> consumers use pure ldmatrix (R14-validated
//    ABF layout). The LDS->split->MMA dependent chain is gone; still ONE
//    barrier per tile.
//  - B: pre-split bf16, 3-stage cp.async ring (unchanged).
//  - MMA order / accumulators / epilogue identical to R13 (exact fp64
//    rescue margin<1e-4 + 1.2e-6 inversion window, R7-locked).

#define KDIM 4096
#define EXP 64
#define BM 64
#define BK 64
#define NT (KDIM / BK)        // 64 tiles
#define THREADS 512

#define MARGIN_EPS 1e-4f
#define INVERT_TAU 1.2e-6

// ---- smem layout (bytes) ----
#define ABF_STRIDE 160                       // 64 bf16 (128B) padded to 160B
#define A_HALF 10240                          // 64 rows x 160B
#define A_STG (2 * A_HALF)                    // hi + lo = 20480
#define OFF_A(s) ((uint32_t)(s) * A_STG)      // stages 0,1 -> 40960
#define B_ROWB 144
#define B_STG 18432                           // hi+lo, 64 x 144B each
#define OFF_BHI(s) (40960u + (uint32_t)(s) * B_STG)
#define OFF_BLO(s) (OFF_BHI(s) + 9216u)
#define SMEM_TOTAL 96256                      // 40960 + 3*18432

__device__ __nv_bfloat16 g_Whi[EXP * KDIM];
__device__ __nv_bfloat16 g_Wlo[EXP * KDIM];

__device__ __forceinline__ uint32_t smem_u32(const void* p) {
    uint32_t a;
    asm("{ .reg .u64 t; cvta.to.shared.u64 t, %1; cvt.u32.u64 %0, t; }"
        : "=r"(a) : "l"(p));
    return a;
}
__device__ __forceinline__ void cp16(uint32_t dst, const void* src) {
    asm volatile("cp.async.cg.shared.global [%0], [%1], 16;"
                 :: "r"(dst), "l"(src) : "memory");
}
#define CP_COMMIT() asm volatile("cp.async.commit_group;" ::: "memory")
#define CP_WAIT1()  asm volatile("cp.async.wait_group 1;" ::: "memory")
#define CP_WAIT0()  asm volatile("cp.async.wait_group 0;" ::: "memory")

__device__ __forceinline__ void sts128(uint32_t addr, const uint32_t* r) {
    asm volatile("st.shared.v4.b32 [%0], {%1,%2,%3,%4};"
                 :: "r"(addr), "r"(r[0]), "r"(r[1]), "r"(r[2]), "r"(r[3])
                 : "memory");
}
__device__ __forceinline__ void ldsm_x4(uint32_t* r, uint32_t addr) {
    asm volatile("ldmatrix.sync.aligned.m8n8.x4.shared.b16 {%0,%1,%2,%3}, [%4];"
                 : "=r"(r[0]), "=r"(r[1]), "=r"(r[2]), "=r"(r[3]) : "r"(addr));
}
__device__ __forceinline__ void mma_bf16(float* c, const uint32_t* a,
                                         uint32_t b0, uint32_t b1) {
    asm volatile(
        "mma.sync.aligned.m16n8k16.row.col.f32.bf16.bf16.f32 "
        "{%0,%1,%2,%3}, {%4,%5,%6,%7}, {%8,%9}, {%0,%1,%2,%3};"
        : "+f"(c[0]), "+f"(c[1]), "+f"(c[2]), "+f"(c[3])
        : "r"(a[0]), "r"(a[1]), "r"(a[2]), "r"(a[3]), "r"(b0), "r"(b1));
}
__device__ __forceinline__ void split2(float fx, float fy,
                                       uint32_t& hi, uint32_t& lo) {
    uint32_t h;
    asm("cvt.rn.bf16x2.f32 %0, %1, %2;" : "=r"(h) : "f"(fy), "f"(fx));
    const float h0 = __uint_as_float(h << 16);
    const float h1 = __uint_as_float(h & 0xffff0000u);
    const float r0 = fx - h0;
    const float r1 = fy - h1;
    asm("cvt.rn.bf16x2.f32 %0, %1, %2;" : "=r"(lo) : "f"(r1), "f"(r0));
    hi = h;
}
__device__ __forceinline__ bool ranks_above(float v1, int i1, float v2, int i2) {
    return (v1 > v2) || (v1 == v2 && i1 < i2);
}

// ---- W prep: split fp32 -> bf16 hi/lo, transpose to [E][K] ----
__global__ void prep_W_kernel(const float* __restrict__ W) {
    int idx = blockIdx.x * blockDim.x + threadIdx.x;
    int e = idx >> 12;
    int k = idx & (KDIM - 1);
    float v = W[(size_t)k * EXP + e];
    __nv_bfloat16 h = __float2bfloat16(v);
    g_Whi[idx] = h;
    g_Wlo[idx] = __float2bfloat16(v - __bfloat162float(h));
}

__global__ __launch_bounds__(THREADS, 2)
void gate_hmma_kernel(const float* __restrict__ x,
                      const float* __restrict__ W,
                      float* __restrict__ y_out,
                      float* __restrict__ logits_out) {
    extern __shared__ __align__(16) char smem[];
    const uint32_t sb = smem_u32(smem);
    const int tid = threadIdx.x;
    const int wid = tid >> 5;
    const int lane = tid & 31;
    const int mwarp = wid & 3;             // rows mwarp*16 .. +15
    const int khalf = (wid >> 2) & 1;      // k-steps {0,1} or {2,3}
    const int nhalf = wid >> 3;            // cols 0-31 or 32-63
    const int block_row = blockIdx.x * BM;

    // ---- A producer: each thread owns 8 fp32 (row = tid>>3, k-chunk tid&7)
    const int pa_row = tid >> 3;
    const int pa_k = (tid & 7) * 8;
    const float* pa_src = x + (size_t)(block_row + pa_row) * KDIM + pa_k;
    const uint32_t pa_dst = (uint32_t)(pa_row * ABF_STRIDE + (tid & 7) * 16);

    // ---- B producer (cp.async, pre-split bf16) ----
    const int p_be = tid >> 3;                 // expert 0..63
    const int p_bp = tid & 7;                  // chunk 0..7
    const __nv_bfloat16* p_bh = g_Whi + (size_t)p_be * KDIM + p_bp * 8;
    const __nv_bfloat16* p_bl = g_Wlo + (size_t)p_be * KDIM + p_bp * 8;
    const uint32_t p_bdst = (uint32_t)(p_be * B_ROWB + p_bp * 16);

    // ---- consumer constants ----
    const uint32_t a_ld =
        (uint32_t)((mwarp * 16 + (lane & 15)) * ABF_STRIDE + (lane >> 4) * 16);
    const int bg = lane >> 3;
    const uint32_t b_ldoff =
        (uint32_t)(((bg >> 1) * 8 + (lane & 7)) * B_ROWB + (bg & 1) * 16);

    float c[4][4];
#pragma unroll
    for (int i = 0; i < 4; ++i)
#pragma unroll
        for (int j = 0; j < 4; ++j) c[i][j] = 0.0f;

    auto issue_B = [&](int t) {
        const int k0 = t * BK;
        const int bs = t % 3;
        cp16(sb + OFF_BHI(bs) + p_bdst, p_bh + k0);
        cp16(sb + OFF_BLO(bs) + p_bdst, p_bl + k0);
        CP_COMMIT();
    };

    // A split+store from registers into bf16 stage s
    auto store_A = [&](const float4& fa, const float4& fb, int s) {
        uint32_t hi[4], lo[4];
        split2(fa.x, fa.y, hi[0], lo[0]);
        split2(fa.z, fa.w, hi[1], lo[1]);
        split2(fb.x, fb.y, hi[2], lo[2]);
        split2(fb.z, fb.w, hi[3], lo[3]);
        sts128(sb + OFF_A(s) + pa_dst, hi);
        sts128(sb + OFF_A(s) + A_HALF + pa_dst, lo);
    };

    // ---- prologue ----
    issue_B(0);
    issue_B(1);
    float4 pa0 = *(const float4*)(pa_src);
    float4 pa1 = *(const float4*)(pa_src + 4);
    store_A(pa0, pa1, 0);                      // A(0) -> stage 0
    pa0 = *(const float4*)(pa_src + BK);
    pa1 = *(const float4*)(pa_src + BK + 4);   // regs hold A(1)

    for (int t = 0; t < NT; ++t) {
        if (t + 2 < NT) CP_WAIT1(); else CP_WAIT0();
        __syncthreads();   // A(t) STS visible; B(t) landed; stage (t+1)&1 free
        if (t + 2 < NT) issue_B(t + 2);

        // ---- split + store A(t+1) (regs held), then prefetch A(t+2) ----
        if (t + 1 < NT) {
            store_A(pa0, pa1, (t + 1) & 1);
            if (t + 2 < NT) {
                const int k0 = (t + 2) * BK;
                pa0 = *(const float4*)(pa_src + k0);
                pa1 = *(const float4*)(pa_src + k0 + 4);
            }
        }

        // ---- MMA phase: pure ldmatrix feeds (R13 order, single acc) ----
        const uint32_t astg = sb + OFF_A(t & 1);
        const int bs = t % 3;
#pragma unroll
        for (int kk = 0; kk < 2; ++kk) {
            const int ks = khalf * 2 + kk;
            uint32_t ahi[4], alo[4];
            ldsm_x4(ahi, astg + a_ld + (uint32_t)(ks * 32));
            ldsm_x4(alo, astg + A_HALF + a_ld + (uint32_t)(ks * 32));
#pragma unroll
            for (int npl = 0; npl < 2; ++npl) {
                const int np = nhalf * 2 + npl;
                uint32_t bh[4], bl[4];
                const uint32_t bo = b_ldoff + (uint32_t)(np * 16 * B_ROWB + ks * 32);
                ldsm_x4(bh, sb + OFF_BHI(bs) + bo);
                ldsm_x4(bl, sb + OFF_BLO(bs) + bo);
                mma_bf16(c[2 * npl],     ahi, bh[0], bh[1]);
                mma_bf16(c[2 * npl],     ahi, bl[0], bl[1]);
                mma_bf16(c[2 * npl],     alo, bh[0], bh[1]);
                mma_bf16(c[2 * npl + 1], ahi, bh[2], bh[3]);
                mma_bf16(c[2 * npl + 1], ahi, bl[2], bl[3]);
                mma_bf16(c[2 * npl + 1], alo, bh[2], bh[3]);
            }
        }
    }

    __syncthreads();   // before red overlay of stage smem

    // ---- dump partials: red1 = khalf0, red2 = khalf1 (stride 65) ----
    float* red1 = (float*)smem;                // 64 x 65 fp32
    float* red2 = red1 + 64 * 65;
    {
        float* buf = khalf ? red2 : red1;
        const int q = lane >> 2;
        const int eb = (lane & 3) * 2;
#pragma unroll
        for (int i = 0; i < 4; ++i)
#pragma unroll
            for (int j = 0; j < 4; ++j) {
                const int row = mwarp * 16 + q + ((j >> 1) << 3);
                const int col = nhalf * 32 + i * 8 + eb + (j & 1);
                buf[row * 65 + col] = c[i][j];
            }
    }
    __syncthreads();

    // ---- epilogue (R9-R15 validated) on warps 0-3 ----
    if (wid < 4) {
        const int q = lane >> 2;
        const int eb = (lane & 3) * 2;
#pragma unroll
        for (int h = 0; h < 2; ++h) {
            const int row = wid * 16 + q + h * 8;
            const int row_g = block_row + row;
            float v[16];
#pragma unroll
            for (int nt = 0; nt < 8; ++nt) {
                const int col = nt * 8 + eb;
                v[2 * nt]     = red1[row * 65 + col]     + red2[row * 65 + col];
                v[2 * nt + 1] = red1[row * 65 + col + 1] + red2[row * 65 + col + 1];
            }

            float* lp = logits_out + (size_t)row_g * EXP;
#pragma unroll
            for (int nt = 0; nt < 8; ++nt)
                *(float2*)(lp + nt * 8 + eb) = make_float2(v[2 * nt], v[2 * nt + 1]);

            float v1 = v[0], v2 = -INFINITY, v3 = -INFINITY;
            int i1 = eb, i2 = 1 << 20, i3 = 1 << 20;
#pragma unroll
            for (int idx = 1; idx < 16; ++idx) {
                const int e = (idx >> 1) * 8 + eb + (idx & 1);
                const float val = v[idx];
                if (ranks_above(val, e, v1, i1)) {
                    v3 = v2; i3 = i2; v2 = v1; i2 = i1; v1 = val; i1 = e;
                } else if (ranks_above(val, e, v2, i2)) {
                    v3 = v2; i3 = i2; v2 = val; i2 = e;
                } else if (ranks_above(val, e, v3, i3)) {
                    v3 = val; i3 = e;
                }
            }
#pragma unroll
            for (int m = 1; m <= 2; m <<= 1) {
                const float b1 = __shfl_xor_sync(0xffffffffu, v1, m);
                const float b2 = __shfl_xor_sync(0xffffffffu, v2, m);
                const float b3 = __shfl_xor_sync(0xffffffffu, v3, m);
                const int j1 = __shfl_xor_sync(0xffffffffu, i1, m);
                const int j2 = __shfl_xor_sync(0xffffffffu, i2, m);
                const int j3 = __shfl_xor_sync(0xffffffffu, i3, m);
                const float bv[3] = {b1, b2, b3};
                const int bi[3] = {j1, j2, j3};
#pragma unroll
                for (int c2 = 0; c2 < 3; ++c2) {
                    const float val = bv[c2]; const int e = bi[c2];
                    if (ranks_above(val, e, v1, i1)) {
                        v3 = v2; i3 = i2; v2 = v1; i2 = i1; v1 = val; i1 = e;
                    } else if (ranks_above(val, e, v2, i2)) {
                        v3 = v2; i3 = i2; v2 = val; i2 = e;
                    } else if (ranks_above(val, e, v3, i3)) {
                        v3 = val; i3 = e;
                    }
                }
            }

            int sel1 = i1, sel2 = i2;

            const bool flag = (eb == 0) && (v2 - v3 < MARGIN_EPS);
            unsigned need = __ballot_sync(0xffffffffu, flag);
            while (need) {
                const int src = __ffs(need) - 1;
                need &= need - 1;
                const int rrow = __shfl_sync(0xffffffffu, row_g, src);
                int cand[3];
                cand[0] = __shfl_sync(0xffffffffu, i1, src);
                cand[1] = __shfl_sync(0xffffffffu, i2, src);
                cand[2] = __shfl_sync(0xffffffffu, i3, src);
                const float* xr = x + (size_t)rrow * KDIM;
                double dv[3];
#pragma unroll
                for (int cc = 0; cc < 3; ++cc) {
                    const int e = cand[cc];
                    double p0 = 0.0, p1 = 0.0, p2 = 0.0, p3 = 0.0;
                    for (int k = lane; k < KDIM; k += 128) {
                        p0 = fma((double)xr[k],      (double)W[(size_t)k * EXP + e],        p0);
                        p1 = fma((double)xr[k + 32], (double)W[(size_t)(k + 32) * EXP + e], p1);
                        p2 = fma((double)xr[k + 64], (double)W[(size_t)(k + 64) * EXP + e], p2);
                        p3 = fma((double)xr[k + 96], (double)W[(size_t)(k + 96) * EXP + e], p3);
                    }
                    double sd = (p0 + p1) + (p2 + p3);
#pragma unroll
                    for (int m = 1; m <= 16; m <<= 1)
                        sd += __shfl_xor_sync(0xffffffffu, sd, m);
                    dv[cc] = sd;
                }
                int ord[3] = {0, 1, 2};
#pragma unroll
                for (int a = 0; a < 2; ++a)
#pragma unroll
                    for (int b = 0; b < 2 - a; ++b) {
                        const int u = ord[b], w = ord[b + 1];
                        const bool above = (dv[u] > dv[w]) ||
                                           (dv[u] == dv[w] && cand[u] < cand[w]);
                        if (!above) { ord[b] = w; ord[b + 1] = u; }
                    }
                const int s1 = cand[ord[0]];
                const int s2 = (dv[ord[1]] - dv[ord[2]] < INVERT_TAU)
                                   ? cand[ord[2]] : cand[ord[1]];
                if ((lane >> 2) == (src >> 2)) { sel1 = s1; sel2 = s2; }
            }

            float ev[16];
            float ssum = 0.0f;
#pragma unroll
            for (int idx = 0; idx < 16; ++idx) {
                ev[idx] = expf(v[idx] - v1);
                ssum += ev[idx];
            }
            ssum += __shfl_xor_sync(0xffffffffu, ssum, 1);
            ssum += __shfl_xor_sync(0xffffffffu, ssum, 2);
            const float inv_s = 1.0f / ssum;

            float* yp = y_out + (size_t)row_g * EXP;
#pragma unroll
            for (int nt = 0; nt < 8; ++nt) {
                const int e0 = nt * 8 + eb, e1 = e0 + 1;
                float2 vy;
                vy.x = (e0 == sel1 || e0 == sel2) ? ev[2 * nt] * inv_s : 0.0f;
                vy.y = (e1 == sel1 || e1 == sel2) ? ev[2 * nt + 1] * inv_s : 0.0f;
                *(float2*)(yp + e0) = vy;
            }
        }
    }
}

extern "C" void kernel_launch(void* const* d_in, const int* in_sizes, int n_in,
                              void* d_out, int out_size) {
    const float* x = (const float*)d_in[0];
    const float* W = (const float*)d_in[1];
    float* out = (float*)d_out;

    const int M = in_sizes[0] / KDIM;          // 16384
    float* y_out = out;                        // first half: y
    float* logits_out = out + (size_t)M * EXP; // second half: logits

    prep_W_kernel<<<(EXP * KDIM) / 256, 256>>>(W);

    cudaFuncSetAttribute(gate_hmma_kernel,
                         cudaFuncAttributeMaxDynamicSharedMemorySize, SMEM_TOTAL);
    gate_hmma_kernel<<<M / BM, THREADS, SMEM_TOTAL>>>(x, W, y_out, logits_out);
}

// round 17
// speedup vs baseline: 1.1297x; 1.1297x over previous
#include <cuda_runtime.h>
#include <cuda_bf16.h>
#include <math.h>
#include <stdint.h>

// Gate_90426241450822: logits = x @ W ; y = softmax(logits) * top2_mask
// x: [M=16384, K=4096] fp32, W: [K=4096, E=64] fp32
// out: [y (M*64) | logits (M*64)] fp32
//
// R17 = R13 pipeline (best: 166us) with SMEM-TRAFFIC-MINIMAL warp tiling:
// 16 warps = 2 M-warps x 2 N-warps x 4 K-quarters, warp tile 32x32xk16.
// B-ldsm volume halves (was 4 M-warps re-reading each B fragment), split2
// ALU halves. 4-way K partials in smem, summed by a 16-warp epilogue
// (same top-3 + exact fp64 rescue margin<1e-4 + 1.2e-6 inversion window).

#define KDIM 4096
#define EXP 64
#define BM 64
#define BK 64
#define NT (KDIM / BK)        // 64 tiles
#define THREADS 512
#define STAGES 3

#define MARGIN_EPS 1e-4f
#define INVERT_TAU 1.2e-6

// stage layout (bytes) — identical to R13
#define A_STG 16384                      // 64 rows x 256B
#define B_ROWB 144
#define B_HALF (EXP * B_ROWB)            // 9216
#define OFF_BHI A_STG
#define OFF_BLO (A_STG + B_HALF)
#define STG_SZ (A_STG + 2 * B_HALF)      // 34816
#define SMEM_TOTAL (STAGES * STG_SZ)     // 104448 (covers 4x 16640B red)

__device__ __nv_bfloat16 g_Whi[EXP * KDIM];
__device__ __nv_bfloat16 g_Wlo[EXP * KDIM];

__device__ __forceinline__ uint32_t smem_u32(const void* p) {
    uint32_t a;
    asm("{ .reg .u64 t; cvta.to.shared.u64 t, %1; cvt.u32.u64 %0, t; }"
        : "=r"(a) : "l"(p));
    return a;
}
__device__ __forceinline__ void cp16(uint32_t dst, const void* src) {
    asm volatile("cp.async.cg.shared.global [%0], [%1], 16;"
                 :: "r"(dst), "l"(src) : "memory");
}
#define CP_COMMIT() asm volatile("cp.async.commit_group;" ::: "memory")
#define CP_WAIT1()  asm volatile("cp.async.wait_group 1;" ::: "memory")
#define CP_WAIT0()  asm volatile("cp.async.wait_group 0;" ::: "memory")

__device__ __forceinline__ float2 lds_f2(uint32_t addr) {
    float2 v;
    asm volatile("ld.shared.v2.f32 {%0,%1}, [%2];"
                 : "=f"(v.x), "=f"(v.y) : "r"(addr));
    return v;
}
__device__ __forceinline__ void ldsm_x4(uint32_t* r, uint32_t addr) {
    asm volatile("ldmatrix.sync.aligned.m8n8.x4.shared.b16 {%0,%1,%2,%3}, [%4];"
                 : "=r"(r[0]), "=r"(r[1]), "=r"(r[2]), "=r"(r[3]) : "r"(addr));
}
__device__ __forceinline__ void mma_bf16(float* c, const uint32_t* a,
                                         uint32_t b0, uint32_t b1) {
    asm volatile(
        "mma.sync.aligned.m16n8k16.row.col.f32.bf16.bf16.f32 "
        "{%0,%1,%2,%3}, {%4,%5,%6,%7}, {%8,%9}, {%0,%1,%2,%3};"
        : "+f"(c[0]), "+f"(c[1]), "+f"(c[2]), "+f"(c[3])
        : "r"(a[0]), "r"(a[1]), "r"(a[2]), "r"(a[3]), "r"(b0), "r"(b1));
}
__device__ __forceinline__ void split2(float2 f, uint32_t& hi, uint32_t& lo) {
    uint32_t h;
    asm("cvt.rn.bf16x2.f32 %0, %1, %2;" : "=r"(h) : "f"(f.y), "f"(f.x));
    const float h0 = __uint_as_float(h << 16);
    const float h1 = __uint_as_float(h & 0xffff0000u);
    const float r0 = f.x - h0;
    const float r1 = f.y - h1;
    asm("cvt.rn.bf16x2.f32 %0, %1, %2;" : "=r"(lo) : "f"(r1), "f"(r0));
    hi = h;
}
__device__ __forceinline__ bool ranks_above(float v1, int i1, float v2, int i2) {
    return (v1 > v2) || (v1 == v2 && i1 < i2);
}

// ---- W prep: split fp32 -> bf16 hi/lo, transpose to [E][K] ----
__global__ void prep_W_kernel(const float* __restrict__ W) {
    int idx = blockIdx.x * blockDim.x + threadIdx.x;
    int e = idx >> 12;
    int k = idx & (KDIM - 1);
    float v = W[(size_t)k * EXP + e];
    __nv_bfloat16 h = __float2bfloat16(v);
    g_Whi[idx] = h;
    g_Wlo[idx] = __float2bfloat16(v - __bfloat162float(h));
}

__global__ __launch_bounds__(THREADS, 2)
void gate_hmma_kernel(const float* __restrict__ x,
                      const float* __restrict__ W,
                      float* __restrict__ y_out,
                      float* __restrict__ logits_out) {
    extern __shared__ __align__(16) char smem[];
    const uint32_t sb = smem_u32(smem);
    const int tid = threadIdx.x;
    const int wid = tid >> 5;
    const int lane = tid & 31;
    const int mw = wid & 1;                // rows mw*32 .. +31
    const int nw = (wid >> 1) & 1;         // cols nw*32 .. +31
    const int kq = wid >> 2;               // k-step kq (0..3) of each tile
    const int block_row = blockIdx.x * BM;

    // ---- producer constants (512 threads, same as R13) ----
    const int p_arow = tid >> 3;
    const int p_acb = (tid & 7) * 2;
    const float* p_asrc = x + (size_t)(block_row + p_arow) * KDIM + p_acb * 4;
    const uint32_t p_aswz = (uint32_t)((p_arow & 3) << 1);
    const uint32_t p_adst = (uint32_t)(p_arow * 256);

    const int p_be = tid >> 3;
    const int p_bp = tid & 7;
    const __nv_bfloat16* p_bh = g_Whi + (size_t)p_be * KDIM + p_bp * 8;
    const __nv_bfloat16* p_bl = g_Wlo + (size_t)p_be * KDIM + p_bp * 8;
    const uint32_t p_bdst = (uint32_t)(p_be * B_ROWB + p_bp * 16);

    // ---- consumer constants ----
    const uint32_t c_rowA = (uint32_t)((mw * 32 + (lane >> 2)) * 256);
    const uint32_t c_swz = (uint32_t)(((lane >> 2) & 3) << 1);
    const int kb = (lane & 3) * 2;
    const int k0c = kq * 16 + kb;
    const uint32_t off0 =
        (((uint32_t)(k0c >> 2) ^ c_swz) << 4) + (uint32_t)((k0c & 3) * 4);
    const uint32_t off8 =
        (((uint32_t)((k0c + 8) >> 2) ^ c_swz) << 4) + (uint32_t)((k0c & 3) * 4);
    const int bg = lane >> 3;
    const uint32_t b_ldoff =
        (uint32_t)(((bg >> 1) * 8 + (lane & 7)) * B_ROWB + (bg & 1) * 16) +
        (uint32_t)(kq * 32);

    float c[2][4][4];   // [m-tile][n8-group][quad]
#pragma unroll
    for (int mt = 0; mt < 2; ++mt)
#pragma unroll
        for (int i = 0; i < 4; ++i)
#pragma unroll
            for (int j = 0; j < 4; ++j) c[mt][i][j] = 0.0f;

    auto issue_tile = [&](int t) {
        const uint32_t stg = sb + (uint32_t)(t % STAGES) * STG_SZ;
        const int k0 = t * BK;
        const float* asrc = p_asrc + k0;
#pragma unroll
        for (int j = 0; j < 2; ++j) {
            const uint32_t cidx = (uint32_t)(p_acb + j);
            cp16(stg + p_adst + ((cidx ^ p_aswz) << 4), asrc + j * 4);
        }
        cp16(stg + OFF_BHI + p_bdst, p_bh + k0);
        cp16(stg + OFF_BLO + p_bdst, p_bl + k0);
        CP_COMMIT();
    };

    issue_tile(0);
    issue_tile(1);

    for (int t = 0; t < NT; ++t) {
        if (t + 2 < NT) CP_WAIT1(); else CP_WAIT0();
        __syncthreads();
        if (t + 2 < NT) issue_tile(t + 2);

        const uint32_t stg = sb + (uint32_t)(t % STAGES) * STG_SZ;

        // ---- A fragments: 2 m16 tiles, single k-step kq ----
        uint32_t ahi[2][4], alo[2][4];
#pragma unroll
        for (int mt = 0; mt < 2; ++mt) {
            const uint32_t rb = stg + c_rowA + (uint32_t)(mt * 16 * 256);
            split2(lds_f2(rb + off0),        ahi[mt][0], alo[mt][0]);
            split2(lds_f2(rb + 2048 + off0), ahi[mt][1], alo[mt][1]);
            split2(lds_f2(rb + off8),        ahi[mt][2], alo[mt][2]);
            split2(lds_f2(rb + 2048 + off8), ahi[mt][3], alo[mt][3]);
        }

        // ---- B per np (limit register liveness), MMA ----
#pragma unroll
        for (int npl = 0; npl < 2; ++npl) {
            const int np = nw * 2 + npl;
            uint32_t bh[4], bl[4];
            const uint32_t bo = b_ldoff + (uint32_t)(np * 16 * B_ROWB);
            ldsm_x4(bh, stg + OFF_BHI + bo);
            ldsm_x4(bl, stg + OFF_BLO + bo);
#pragma unroll
            for (int mt = 0; mt < 2; ++mt) {
                mma_bf16(c[mt][2 * npl],     ahi[mt], bh[0], bh[1]);
                mma_bf16(c[mt][2 * npl],     ahi[mt], bl[0], bl[1]);
                mma_bf16(c[mt][2 * npl],     alo[mt], bh[0], bh[1]);
                mma_bf16(c[mt][2 * npl + 1], ahi[mt], bh[2], bh[3]);
                mma_bf16(c[mt][2 * npl + 1], ahi[mt], bl[2], bl[3]);
                mma_bf16(c[mt][2 * npl + 1], alo[mt], bh[2], bh[3]);
            }
        }
    }

    __syncthreads();   // before red overlay of stage smem

    // ---- dump partials: 4 k-quarter buffers (stride 65) ----
    float* redb = (float*)smem;                 // 4 x (64 x 65) fp32
    {
        float* buf = redb + kq * (64 * 65);
        const int q = lane >> 2;
        const int eb = (lane & 3) * 2;
#pragma unroll
        for (int mt = 0; mt < 2; ++mt)
#pragma unroll
            for (int i = 0; i < 4; ++i)
#pragma unroll
                for (int j = 0; j < 4; ++j) {
                    const int row = mw * 32 + mt * 16 + q + ((j >> 1) << 3);
                    const int col = nw * 32 + i * 8 + eb + (j & 1);
                    buf[row * 65 + col] = c[mt][i][j];
                }
    }
    __syncthreads();

    // ---- epilogue on ALL 16 warps: warp handles rows wid*4 .. +3 ----
    {
        const int g = lane >> 3;               // row group 0..3
        const int li = lane & 7;               // 8 lanes per row
        const int row = wid * 4 + g;
        const int row_g = block_row + row;
        float v[8];
#pragma unroll
        for (int j = 0; j < 8; ++j) {
            const int col = li * 8 + j;
            v[j] = (redb[row * 65 + col] + redb[64 * 65 + row * 65 + col]) +
                   (redb[2 * 64 * 65 + row * 65 + col] +
                    redb[3 * 64 * 65 + row * 65 + col]);
        }

        float* lp = logits_out + (size_t)row_g * EXP + li * 8;
        *(float4*)(lp)     = make_float4(v[0], v[1], v[2], v[3]);
        *(float4*)(lp + 4) = make_float4(v[4], v[5], v[6], v[7]);

        // local top-3 over 8 cols (e = li*8 + j)
        float v1 = v[0], v2 = -INFINITY, v3 = -INFINITY;
        int i1 = li * 8, i2 = 1 << 20, i3 = 1 << 20;
#pragma unroll
        for (int j = 1; j < 8; ++j) {
            const int e = li * 8 + j;
            const float val = v[j];
            if (ranks_above(val, e, v1, i1)) {
                v3 = v2; i3 = i2; v2 = v1; i2 = i1; v1 = val; i1 = e;
            } else if (ranks_above(val, e, v2, i2)) {
                v3 = v2; i3 = i2; v2 = val; i2 = e;
            } else if (ranks_above(val, e, v3, i3)) {
                v3 = val; i3 = e;
            }
        }
        // merge across 8-lane row group (xor 1,2,4)
#pragma unroll
        for (int m = 1; m <= 4; m <<= 1) {
            const float b1 = __shfl_xor_sync(0xffffffffu, v1, m);
            const float b2 = __shfl_xor_sync(0xffffffffu, v2, m);
            const float b3 = __shfl_xor_sync(0xffffffffu, v3, m);
            const int j1 = __shfl_xor_sync(0xffffffffu, i1, m);
            const int j2 = __shfl_xor_sync(0xffffffffu, i2, m);
            const int j3 = __shfl_xor_sync(0xffffffffu, i3, m);
            const float bv[3] = {b1, b2, b3};
            const int bi[3] = {j1, j2, j3};
#pragma unroll
            for (int c2 = 0; c2 < 3; ++c2) {
                const float val = bv[c2]; const int e = bi[c2];
                if (ranks_above(val, e, v1, i1)) {
                    v3 = v2; i3 = i2; v2 = v1; i2 = i1; v1 = val; i1 = e;
                } else if (ranks_above(val, e, v2, i2)) {
                    v3 = v2; i3 = i2; v2 = val; i2 = e;
                } else if (ranks_above(val, e, v3, i3)) {
                    v3 = val; i3 = e;
                }
            }
        }

        int sel1 = i1, sel2 = i2;

        // ---- warp-cooperative exact fp64 rescue ----
        const bool flag = (li == 0) && (v2 - v3 < MARGIN_EPS);
        unsigned need = __ballot_sync(0xffffffffu, flag);
        while (need) {
            const int src = __ffs(need) - 1;
            need &= need - 1;
            const int rrow = __shfl_sync(0xffffffffu, row_g, src);
            int cand[3];
            cand[0] = __shfl_sync(0xffffffffu, i1, src);
            cand[1] = __shfl_sync(0xffffffffu, i2, src);
            cand[2] = __shfl_sync(0xffffffffu, i3, src);
            const float* xr = x + (size_t)rrow * KDIM;
            double dv[3];
#pragma unroll
            for (int cc = 0; cc < 3; ++cc) {
                const int e = cand[cc];
                double p0 = 0.0, p1 = 0.0, p2 = 0.0, p3 = 0.0;
                for (int k = lane; k < KDIM; k += 128) {
                    p0 = fma((double)xr[k],      (double)W[(size_t)k * EXP + e],        p0);
                    p1 = fma((double)xr[k + 32], (double)W[(size_t)(k + 32) * EXP + e], p1);
                    p2 = fma((double)xr[k + 64], (double)W[(size_t)(k + 64) * EXP + e], p2);
                    p3 = fma((double)xr[k + 96], (double)W[(size_t)(k + 96) * EXP + e], p3);
                }
                double sd = (p0 + p1) + (p2 + p3);
#pragma unroll
                for (int m = 1; m <= 16; m <<= 1)
                    sd += __shfl_xor_sync(0xffffffffu, sd, m);
                dv[cc] = sd;
            }
            int ord[3] = {0, 1, 2};
#pragma unroll
            for (int a = 0; a < 2; ++a)
#pragma unroll
                for (int b = 0; b < 2 - a; ++b) {
                    const int u = ord[b], w = ord[b + 1];
                    const bool above = (dv[u] > dv[w]) ||
                                       (dv[u] == dv[w] && cand[u] < cand[w]);
                    if (!above) { ord[b] = w; ord[b + 1] = u; }
                }
            const int s1 = cand[ord[0]];
            const int s2 = (dv[ord[1]] - dv[ord[2]] < INVERT_TAU)
                               ? cand[ord[2]] : cand[ord[1]];
            if (g == (src >> 3)) { sel1 = s1; sel2 = s2; }
        }

        // ---- softmax + top-2 mask ----
        float ev[8];
        float ssum = 0.0f;
#pragma unroll
        for (int j = 0; j < 8; ++j) {
            ev[j] = expf(v[j] - v1);
            ssum += ev[j];
        }
#pragma unroll
        for (int m = 1; m <= 4; m <<= 1)
            ssum += __shfl_xor_sync(0xffffffffu, ssum, m);
        const float inv_s = 1.0f / ssum;

        float4 y0, y1;
        const int e0 = li * 8;
        y0.x = (e0 + 0 == sel1 || e0 + 0 == sel2) ? ev[0] * inv_s : 0.0f;
        y0.y = (e0 + 1 == sel1 || e0 + 1 == sel2) ? ev[1] * inv_s : 0.0f;
        y0.z = (e0 + 2 == sel1 || e0 + 2 == sel2) ? ev[2] * inv_s : 0.0f;
        y0.w = (e0 + 3 == sel1 || e0 + 3 == sel2) ? ev[3] * inv_s : 0.0f;
        y1.x = (e0 + 4 == sel1 || e0 + 4 == sel2) ? ev[4] * inv_s : 0.0f;
        y1.y = (e0 + 5 == sel1 || e0 + 5 == sel2) ? ev[5] * inv_s : 0.0f;
        y1.z = (e0 + 6 == sel1 || e0 + 6 == sel2) ? ev[6] * inv_s : 0.0f;
        y1.w = (e0 + 7 == sel1 || e0 + 7 == sel2) ? ev[7] * inv_s : 0.0f;
        float* yp = y_out + (size_t)row_g * EXP + e0;
        *(float4*)(yp)     = y0;
        *(float4*)(yp + 4) = y1;
    }
}

extern "C" void kernel_launch(void* const* d_in, const int* in_sizes, int n_in,
                              void* d_out, int out_size) {
    const float* x = (const float*)d_in[0];
    const float* W = (const float*)d_in[1];
    float* out = (float*)d_out;

    const int M = in_sizes[0] / KDIM;          // 16384
    float* y_out = out;                        // first half: y
    float* logits_out = out + (size_t)M * EXP; // second half: logits

    prep_W_kernel<<<(EXP * KDIM) / 256, 256>>>(W);

    cudaFuncSetAttribute(gate_hmma_kernel,
                         cudaFuncAttributeMaxDynamicSharedMemorySize, SMEM_TOTAL);
    gate_hmma_kernel<<<M / BM, THREADS, SMEM_TOTAL>>>(x, W, y_out, logits_out);
}